// round 1
// baseline (speedup 1.0000x reference)
#include <cuda_runtime.h>
#include <math.h>

#define BB 256
#define HDN 1024
#define HWN 4096
#define NP 16

// ---------------- scratch (device globals: no allocation allowed) ----------------
__device__ float  g_hid1[BB * HDN];
__device__ float  g_hid2[BB * HDN];
__device__ float  g_part[NP * 256];      // 16 part images, 16x16 each
__device__ float4 g_params[BB * NP];     // per (b,k): cos, sin, tx, ty
__device__ float4 g_gpar[BB];            // per b: cos, sin, tx, ty (global transform)
__device__ float  g_x[BB * 4096];        // composited image before global transform

// ---------------- 1) part decode: sigmoid(colsum(Wz)) ----------------
__global__ __launch_bounds__(256) void part_kernel(const float* __restrict__ Wz) {
    int i = blockIdx.x * 256 + threadIdx.x;   // 0..4095
    float s = 0.0f;
#pragma unroll
    for (int z = 0; z < 32; z++) s += Wz[z * 4096 + i];
    g_part[i] = 1.0f / (1.0f + expf(-s));
}

// ---------------- 2) fp32 tiled GEMM: C = relu(A[MxK] @ B[KxN] + bias) ----------------
// tile 32(M) x 64(N), BK=32, 256 threads, 2x4 microtile
__global__ __launch_bounds__(256) void gemm_bias_relu(
    const float* __restrict__ A, const float* __restrict__ B,
    const float* __restrict__ bias, float* __restrict__ C,
    int M, int N, int K, int relu)
{
    __shared__ float As[32][33];
    __shared__ float Bs[32][64];
    int t  = threadIdx.x;
    int m0 = blockIdx.y * 32;
    int n0 = blockIdx.x * 64;

    int am = t >> 3;            // 0..31
    int ak = (t & 7) * 4;       // 0..28
    int bk = t >> 4;            // 0..15
    int bn = (t & 15) * 4;      // 0..60
    int row = (t >> 4) * 2;     // 0..30
    int col = (t & 15) * 4;     // 0..60

    float acc[2][4];
#pragma unroll
    for (int r = 0; r < 2; r++)
#pragma unroll
        for (int c = 0; c < 4; c++) acc[r][c] = 0.0f;

    for (int k0 = 0; k0 < K; k0 += 32) {
        float4 av = *(const float4*)(A + (m0 + am) * K + k0 + ak);
        As[ak + 0][am] = av.x; As[ak + 1][am] = av.y;
        As[ak + 2][am] = av.z; As[ak + 3][am] = av.w;
        float4 bv0 = *(const float4*)(B + (k0 + bk) * N + n0 + bn);
        float4 bv1 = *(const float4*)(B + (k0 + bk + 16) * N + n0 + bn);
        *(float4*)&Bs[bk][bn]      = bv0;
        *(float4*)&Bs[bk + 16][bn] = bv1;
        __syncthreads();
#pragma unroll
        for (int kk = 0; kk < 32; kk++) {
            float a0 = As[kk][row], a1 = As[kk][row + 1];
            float4 b4 = *(float4*)&Bs[kk][col];
            acc[0][0] += a0 * b4.x; acc[0][1] += a0 * b4.y;
            acc[0][2] += a0 * b4.z; acc[0][3] += a0 * b4.w;
            acc[1][0] += a1 * b4.x; acc[1][1] += a1 * b4.y;
            acc[1][2] += a1 * b4.z; acc[1][3] += a1 * b4.w;
        }
        __syncthreads();
    }

    float4 bb = *(const float4*)&bias[n0 + col];
#pragma unroll
    for (int r = 0; r < 2; r++) {
        float4 v;
        v.x = acc[r][0] + bb.x; v.y = acc[r][1] + bb.y;
        v.z = acc[r][2] + bb.z; v.w = acc[r][3] + bb.w;
        if (relu) {
            v.x = fmaxf(v.x, 0.0f); v.y = fmaxf(v.y, 0.0f);
            v.z = fmaxf(v.z, 0.0f); v.w = fmaxf(v.w, 0.0f);
        }
        *(float4*)&C[(m0 + row + r) * N + n0 + col] = v;
    }
}

// ---------------- 3) heads: u-sample per part, global sample, -> rot/trans params ----------------
__global__ __launch_bounds__(128) void heads_kernel(
    const float* __restrict__ Wum, const float* __restrict__ bum,
    const float* __restrict__ Wuv, const float* __restrict__ buv,
    const float* __restrict__ Wgm, const float* __restrict__ bgm,
    const float* __restrict__ Wgv, const float* __restrict__ bgv,
    const float* __restrict__ eps_u, const float* __restrict__ eps_g)
{
    __shared__ float sh[HDN];
    __shared__ float su[48];
    __shared__ float sg[3];
    int b = blockIdx.x, t = threadIdx.x;
    const float* hrow = g_hid2 + b * HDN;
    for (int i = t; i < HDN; i += 128) sh[i] = hrow[i];
    __syncthreads();

    if (t < 48) {
        float du = 0.0f, dv = 0.0f;
        for (int i = 0; i < HDN; i++) {
            float h = sh[i];
            du += h * Wum[i * 48 + t];
            dv += h * Wuv[i * 48 + t];
        }
        float umu = tanhf(du + bum[t]);
        float up  = dv + buv[t];
        float uvar = expf(up > -6.0f ? up : -6.0f);        // threshold(x,-6,-6)
        su[t] = umu + uvar * eps_u[b * 48 + t];
    } else if (t < 51) {
        int j = t - 48;
        float dm = 0.0f, dv = 0.0f;
        for (int i = 0; i < HDN; i++) {
            float h = sh[i];
            dm += h * Wgm[i * 3 + j];
            dv += h * Wgv[i * 3 + j];
        }
        float gmu = tanhf(dm + bgm[j]);
        float gp  = dv + bgv[j];
        float gvar = expf(gp > -6.0f ? gp : 6.0f);         // threshold(x,-6,6) !
        sg[j] = gmu + gvar * eps_g[b * 3 + j];
    }
    __syncthreads();

    if (t < 16) {
        float a = su[3 * t], tx = su[3 * t + 1], ty = su[3 * t + 2];
        g_params[b * 16 + t] = make_float4(cosf(a), sinf(a), tx, ty);
    } else if (t == 16) {
        g_gpar[b] = make_float4(cosf(sg[0]), sinf(sg[0]), sg[1], sg[2]);
    }
}

// ---------------- 4) fused composite: KM chain + part chain + weighted sum over P ----------------
// One block per batch b. 256 threads: w = t&63, each thread owns 16 rows.
__global__ __launch_bounds__(256) void composite_kernel(const float* __restrict__ M)
{
    __shared__ float  sparts[NP][256];
    __shared__ float4 spar[NP];
    int b = blockIdx.x, t = threadIdx.x;
    for (int i = t; i < NP * 256; i += 256) sparts[i >> 8][i & 255] = g_part[i];
    if (t < 16) spar[t] = g_params[b * 16 + t];
    __syncthreads();

    int w  = t & 63;
    int hb = (t >> 6) * 16;
    float num[16], den[16];
#pragma unroll
    for (int i = 0; i < 16; i++) { num[i] = 0.0f; den[i] = 0.0f; }
    float xn = (2 * w + 1) * (1.0f / 64.0f) - 1.0f;

#pragma unroll 1
    for (int k = 0; k < 16; k++) {
        float4 pp = spar[k];
        float c = pp.x, s = pp.y, tx = pp.z, ty = pp.w;
        int sx = (k & 3) * 8 - 12;       // anchor shift in px: {-12,-4,4,12}
        int sy = (k >> 2) * 8 - 12;

        // KM: translation-only sample composed with the integer anchor shift of M
        float fx = fminf(fmaxf(tx * 32.0f, -1e8f), 1e8f);
        float fy = fminf(fmaxf(ty * 32.0f, -1e8f), 1e8f);
        float ffx = floorf(fx), ffy = floorf(fy);
        float wx = fx - ffx, wy = fy - ffy;
        int dx0 = (int)ffx, dy0 = (int)ffy;
        int x0 = w + dx0, xA = x0 + sx;
        bool vx0 = ((unsigned)x0 < 64u) && ((unsigned)xA < 64u);
        bool vx1 = ((unsigned)(x0 + 1) < 64u) && ((unsigned)(xA + 1) < 64u);
        const float* Mk = M + ((size_t)((b << 4) + k) << 12);

        // xp: rotation+translation sample of anchored part (window [iox,iox+16))
        float gxc = c * xn + tx;
        float gyc = s * xn + ty;
        int iox = 24 - sx, ioy = 24 - sy;
        float foxlo = (float)iox - 1.0f, foxhi = (float)iox + 16.0f;
        float foylo = (float)ioy - 1.0f, foyhi = (float)ioy + 16.0f;
        const float* pk = &sparts[k][0];

#pragma unroll
        for (int i = 0; i < 16; i++) {
            int h = hb + i;
            // --- KM sample (constant weights per (b,k), coalesced loads of M) ---
            int y0 = h + dy0, yA = y0 + sy;
            bool vy0 = ((unsigned)y0 < 64u) && ((unsigned)yA < 64u);
            bool vy1 = ((unsigned)(y0 + 1) < 64u) && ((unsigned)(yA + 1) < 64u);
            float m00 = 0.0f, m01 = 0.0f, m10 = 0.0f, m11 = 0.0f;
            if (vy0) {
                const float* r = Mk + yA * 64 + xA;
                if (vx0) m00 = r[0];
                if (vx1) m01 = r[1];
            }
            if (vy1) {
                const float* r = Mk + (yA + 1) * 64 + xA;
                if (vx0) m10 = r[0];
                if (vx1) m11 = r[1];
            }
            float r0 = m00 + wx * (m01 - m00);
            float r1 = m10 + wx * (m11 - m10);
            float km = r0 + wy * (r1 - r0);
            den[i] += km;

            // --- xp sample (skippable outside the rotated 17x17 window) ---
            float yn  = (2 * h + 1) * (1.0f / 64.0f) - 1.0f;
            float gx  = gxc - s * yn;
            float gy  = gyc + c * yn;
            float ppx = gx * 32.0f + 31.5f;
            float ppy = gy * 32.0f + 31.5f;
            if (ppx > foxlo && ppx < foxhi && ppy > foylo && ppy < foyhi) {
                float fjx = floorf(ppx), fjy = floorf(ppy);
                float ux = ppx - fjx, uy = ppy - fjy;
                int px0 = (int)fjx - iox, py0 = (int)fjy - ioy;
                float p00 = 0.0f, p01 = 0.0f, p10 = 0.0f, p11 = 0.0f;
                if ((unsigned)py0 < 16u) {
                    if ((unsigned)px0 < 16u)       p00 = pk[py0 * 16 + px0];
                    if ((unsigned)(px0 + 1) < 16u) p01 = pk[py0 * 16 + px0 + 1];
                }
                if ((unsigned)(py0 + 1) < 16u) {
                    if ((unsigned)px0 < 16u)       p10 = pk[(py0 + 1) * 16 + px0];
                    if ((unsigned)(px0 + 1) < 16u) p11 = pk[(py0 + 1) * 16 + px0 + 1];
                }
                float q0 = p00 + ux * (p01 - p00);
                float q1 = p10 + ux * (p11 - p10);
                float xp = q0 + uy * (q1 - q0);
                num[i] += xp * km;
            }
        }
    }

    float* xb = g_x + b * 4096 + w;
#pragma unroll
    for (int i = 0; i < 16; i++) {
        float d = den[i];
        d = (d == 0.0f) ? 1.0f : d;
        xb[(hb + i) * 64] = num[i] / d;
    }
}

// ---------------- 5) global transform: bilinear resample of composited image ----------------
__global__ __launch_bounds__(256) void global_kernel(float* __restrict__ out)
{
    int b = blockIdx.x, t = threadIdx.x;
    int w = t & 63;
    int h = blockIdx.y * 4 + (t >> 6);
    float4 gp = g_gpar[b];
    float xn = (2 * w + 1) * (1.0f / 64.0f) - 1.0f;
    float yn = (2 * h + 1) * (1.0f / 64.0f) - 1.0f;
    float gx = gp.x * xn - gp.y * yn + gp.z;
    float gy = gp.y * xn + gp.x * yn + gp.w;
    float px = fminf(fmaxf(gx * 32.0f + 31.5f, -8.0f), 72.0f);
    float py = fminf(fmaxf(gy * 32.0f + 31.5f, -8.0f), 72.0f);
    float fx0 = floorf(px), fy0 = floorf(py);
    float wx = px - fx0, wy = py - fy0;
    int x0 = (int)fx0, y0 = (int)fy0;
    const float* xb = g_x + b * 4096;
    float v00 = 0.0f, v01 = 0.0f, v10 = 0.0f, v11 = 0.0f;
    bool vx0 = (unsigned)x0 < 64u, vx1 = (unsigned)(x0 + 1) < 64u;
    bool vy0 = (unsigned)y0 < 64u, vy1 = (unsigned)(y0 + 1) < 64u;
    if (vx0 && vy0) v00 = xb[y0 * 64 + x0];
    if (vx1 && vy0) v01 = xb[y0 * 64 + x0 + 1];
    if (vx0 && vy1) v10 = xb[(y0 + 1) * 64 + x0];
    if (vx1 && vy1) v11 = xb[(y0 + 1) * 64 + x0 + 1];
    float r0 = v00 + wx * (v01 - v00);
    float r1 = v10 + wx * (v11 - v10);
    out[b * 4096 + h * 64 + w] = r0 + wy * (r1 - r0);
}

// ---------------- launch ----------------
extern "C" void kernel_launch(void* const* d_in, const int* in_sizes, int n_in,
                              void* d_out, int out_size)
{
    const float* inputs = (const float*)d_in[0];
    const float* W1     = (const float*)d_in[1];
    const float* b1     = (const float*)d_in[2];
    const float* W2     = (const float*)d_in[3];
    const float* b2     = (const float*)d_in[4];
    const float* Wum    = (const float*)d_in[5];
    const float* bum    = (const float*)d_in[6];
    const float* Wuv    = (const float*)d_in[7];
    const float* buv    = (const float*)d_in[8];
    const float* Wgm    = (const float*)d_in[9];
    const float* bgm    = (const float*)d_in[10];
    const float* Wgv    = (const float*)d_in[11];
    const float* bgv    = (const float*)d_in[12];
    const float* Wz     = (const float*)d_in[13];
    const float* M      = (const float*)d_in[14];
    const float* eps_u  = (const float*)d_in[15];
    const float* eps_g  = (const float*)d_in[16];
    float* out = (float*)d_out;

    float *hid1, *hid2;
    cudaGetSymbolAddress((void**)&hid1, g_hid1);
    cudaGetSymbolAddress((void**)&hid2, g_hid2);

    part_kernel<<<16, 256>>>(Wz);
    gemm_bias_relu<<<dim3(HDN / 64, BB / 32), 256>>>(inputs, W1, b1, hid1, BB, HDN, HWN, 1);
    gemm_bias_relu<<<dim3(HDN / 64, BB / 32), 256>>>(hid1, W2, b2, hid2, BB, HDN, HDN, 1);
    heads_kernel<<<BB, 128>>>(Wum, bum, Wuv, buv, Wgm, bgm, Wgv, bgv, eps_u, eps_g);
    composite_kernel<<<BB, 256>>>(M);
    global_kernel<<<dim3(BB, 16), 256>>>(out);
}

// round 2
// speedup vs baseline: 1.1917x; 1.1917x over previous
#include <cuda_runtime.h>
#include <math.h>

#define BB 256
#define HDN 1024
#define HWN 4096
#define NP 16

// ---------------- scratch (device globals: no allocation allowed) ----------------
__device__ float  g_hid1[BB * HDN];
__device__ float  g_hid2[BB * HDN];
__device__ float  g_part[NP * 256];      // 16 part images, 16x16 each
__device__ float4 g_params[BB * NP];     // per (b,k): cos, sin, tx, ty
__device__ float4 g_gpar[BB];            // per b: cos, sin, tx, ty (global transform)
__device__ float  g_x[BB * 4096];        // composited image before global transform

// ---------------- 1) part decode: sigmoid(colsum(Wz)) ----------------
__global__ __launch_bounds__(256) void part_kernel(const float* __restrict__ Wz) {
    int i = blockIdx.x * 256 + threadIdx.x;   // 0..4095
    float s = 0.0f;
#pragma unroll
    for (int z = 0; z < 32; z++) s += Wz[z * 4096 + i];
    g_part[i] = 1.0f / (1.0f + expf(-s));
}

// ---------------- 2) fp32 tiled GEMM: C = relu(A[MxK] @ B[KxN] + bias) ----------------
// tile 32(M) x 64(N), BK=32, 256 threads, 2x4 microtile
__global__ __launch_bounds__(256) void gemm_bias_relu(
    const float* __restrict__ A, const float* __restrict__ B,
    const float* __restrict__ bias, float* __restrict__ C,
    int M, int N, int K, int relu)
{
    __shared__ float As[32][33];
    __shared__ float Bs[32][64];
    int t  = threadIdx.x;
    int m0 = blockIdx.y * 32;
    int n0 = blockIdx.x * 64;

    int am = t >> 3;            // 0..31
    int ak = (t & 7) * 4;       // 0..28
    int bk = t >> 4;            // 0..15
    int bn = (t & 15) * 4;      // 0..60
    int row = (t >> 4) * 2;     // 0..30
    int col = (t & 15) * 4;     // 0..60

    float acc[2][4];
#pragma unroll
    for (int r = 0; r < 2; r++)
#pragma unroll
        for (int c = 0; c < 4; c++) acc[r][c] = 0.0f;

    for (int k0 = 0; k0 < K; k0 += 32) {
        float4 av = *(const float4*)(A + (m0 + am) * K + k0 + ak);
        As[ak + 0][am] = av.x; As[ak + 1][am] = av.y;
        As[ak + 2][am] = av.z; As[ak + 3][am] = av.w;
        float4 bv0 = *(const float4*)(B + (k0 + bk) * N + n0 + bn);
        float4 bv1 = *(const float4*)(B + (k0 + bk + 16) * N + n0 + bn);
        *(float4*)&Bs[bk][bn]      = bv0;
        *(float4*)&Bs[bk + 16][bn] = bv1;
        __syncthreads();
#pragma unroll
        for (int kk = 0; kk < 32; kk++) {
            float a0 = As[kk][row], a1 = As[kk][row + 1];
            float4 b4 = *(float4*)&Bs[kk][col];
            acc[0][0] += a0 * b4.x; acc[0][1] += a0 * b4.y;
            acc[0][2] += a0 * b4.z; acc[0][3] += a0 * b4.w;
            acc[1][0] += a1 * b4.x; acc[1][1] += a1 * b4.y;
            acc[1][2] += a1 * b4.z; acc[1][3] += a1 * b4.w;
        }
        __syncthreads();
    }

    float4 bb = *(const float4*)&bias[n0 + col];
#pragma unroll
    for (int r = 0; r < 2; r++) {
        float4 v;
        v.x = acc[r][0] + bb.x; v.y = acc[r][1] + bb.y;
        v.z = acc[r][2] + bb.z; v.w = acc[r][3] + bb.w;
        if (relu) {
            v.x = fmaxf(v.x, 0.0f); v.y = fmaxf(v.y, 0.0f);
            v.z = fmaxf(v.z, 0.0f); v.w = fmaxf(v.w, 0.0f);
        }
        *(float4*)&C[(m0 + row + r) * N + n0 + col] = v;
    }
}

// ---------------- 3) heads v2: outer-product mini-GEMM, 2 batches/block ----------------
// Output per batch: 102 dots of K=1024: [0,48)=umu, [48,96)=uvar, [96,99)=gmu, [99,102)=gvar.
// Block: 256 threads. Thread t<204: (column j = t%102, K-half = t/102), K=512 each.
// Weight rows are read coalesced (consecutive j -> consecutive floats within a row).
__global__ __launch_bounds__(256) void heads_kernel(
    const float* __restrict__ Wum, const float* __restrict__ bum,
    const float* __restrict__ Wuv, const float* __restrict__ buv,
    const float* __restrict__ Wgm, const float* __restrict__ bgm,
    const float* __restrict__ Wgv, const float* __restrict__ bgv,
    const float* __restrict__ eps_u, const float* __restrict__ eps_g)
{
    __shared__ float sh[2][HDN];
    __shared__ float spart[2][204];
    __shared__ float sres[2][102];
    __shared__ float su[2][48];
    __shared__ float sg[2][3];

    int b0 = blockIdx.x * 2;
    int t  = threadIdx.x;

    // load the two hid rows (float4, fully coalesced)
    {
        const float4* h0 = (const float4*)(g_hid2 + (size_t)b0 * HDN);
        const float4* h1 = (const float4*)(g_hid2 + (size_t)(b0 + 1) * HDN);
        ((float4*)sh[0])[t] = h0[t];
        ((float4*)sh[1])[t] = h1[t];
    }
    __syncthreads();

    if (t < 204) {
        int half = (t >= 102) ? 1 : 0;
        int j    = t - half * 102;
        const float* Wp; int stride;
        if (j < 48)      { Wp = Wum + j;        stride = 48; }
        else if (j < 96) { Wp = Wuv + (j - 48); stride = 48; }
        else if (j < 99) { Wp = Wgm + (j - 96); stride = 3;  }
        else             { Wp = Wgv + (j - 99); stride = 3;  }
        int k0 = half * 512;
        const float* wp = Wp + (size_t)k0 * stride;
        const float* h0 = &sh[0][k0];
        const float* h1 = &sh[1][k0];
        float a00 = 0.f, a01 = 0.f, a02 = 0.f, a03 = 0.f;
        float a10 = 0.f, a11 = 0.f, a12 = 0.f, a13 = 0.f;
#pragma unroll 4
        for (int i = 0; i < 512; i += 4) {
            float w0 = wp[(i + 0) * stride];
            float w1 = wp[(i + 1) * stride];
            float w2 = wp[(i + 2) * stride];
            float w3 = wp[(i + 3) * stride];
            a00 += h0[i + 0] * w0; a01 += h0[i + 1] * w1;
            a02 += h0[i + 2] * w2; a03 += h0[i + 3] * w3;
            a10 += h1[i + 0] * w0; a11 += h1[i + 1] * w1;
            a12 += h1[i + 2] * w2; a13 += h1[i + 3] * w3;
        }
        spart[0][t] = (a00 + a01) + (a02 + a03);
        spart[1][t] = (a10 + a11) + (a12 + a13);
    }
    __syncthreads();

    if (t < 204) {
        int bb = (t >= 102) ? 1 : 0;
        int j  = t - bb * 102;
        sres[bb][j] = spart[bb][j] + spart[bb][j + 102];
    }
    __syncthreads();

    // epilogue: t encodes (bb, col)
    {
        int bb = t >> 7;            // 0 or 1 (t<256)
        int j  = t & 127;
        if (j < 48) {
            float umu  = tanhf(sres[bb][j] + bum[j]);
            float up   = sres[bb][48 + j] + buv[j];
            float uvar = expf(up > -6.0f ? up : -6.0f);    // threshold(x,-6,-6)
            su[bb][j]  = umu + uvar * eps_u[(b0 + bb) * 48 + j];
        } else if (j < 51) {
            int j2 = j - 48;
            float gmu  = tanhf(sres[bb][96 + j2] + bgm[j2]);
            float gp   = sres[bb][99 + j2] + bgv[j2];
            float gvar = expf(gp > -6.0f ? gp : 6.0f);     // threshold(x,-6,6) !
            sg[bb][j2] = gmu + gvar * eps_g[(b0 + bb) * 3 + j2];
        }
    }
    __syncthreads();

    {
        int bb = t >> 7;
        int j  = t & 127;
        if (j < 16) {
            float a  = su[bb][3 * j];
            float tx = su[bb][3 * j + 1];
            float ty = su[bb][3 * j + 2];
            g_params[(b0 + bb) * 16 + j] = make_float4(cosf(a), sinf(a), tx, ty);
        } else if (j == 16) {
            g_gpar[b0 + bb] = make_float4(cosf(sg[bb][0]), sinf(sg[bb][0]), sg[bb][1], sg[bb][2]);
        }
    }
}

// ---------------- 4) fused composite: KM chain + part chain + weighted sum over P ----------------
// One block per batch b. 256 threads: w = t&63, each thread owns 16 rows.
__global__ __launch_bounds__(256) void composite_kernel(const float* __restrict__ M)
{
    __shared__ float  sparts[NP][256];
    __shared__ float4 spar[NP];
    int b = blockIdx.x, t = threadIdx.x;
    for (int i = t; i < NP * 256; i += 256) sparts[i >> 8][i & 255] = g_part[i];
    if (t < 16) spar[t] = g_params[b * 16 + t];
    __syncthreads();

    int w  = t & 63;
    int hb = (t >> 6) * 16;
    float num[16], den[16];
#pragma unroll
    for (int i = 0; i < 16; i++) { num[i] = 0.0f; den[i] = 0.0f; }
    float xn = (2 * w + 1) * (1.0f / 64.0f) - 1.0f;

#pragma unroll 1
    for (int k = 0; k < 16; k++) {
        float4 pp = spar[k];
        float c = pp.x, s = pp.y, tx = pp.z, ty = pp.w;
        int sx = (k & 3) * 8 - 12;       // anchor shift in px: {-12,-4,4,12}
        int sy = (k >> 2) * 8 - 12;

        // KM: translation-only sample composed with the integer anchor shift of M
        float fx = fminf(fmaxf(tx * 32.0f, -1e8f), 1e8f);
        float fy = fminf(fmaxf(ty * 32.0f, -1e8f), 1e8f);
        float ffx = floorf(fx), ffy = floorf(fy);
        float wx = fx - ffx, wy = fy - ffy;
        int dx0 = (int)ffx, dy0 = (int)ffy;
        int x0 = w + dx0, xA = x0 + sx;
        bool vx0 = ((unsigned)x0 < 64u) && ((unsigned)xA < 64u);
        bool vx1 = ((unsigned)(x0 + 1) < 64u) && ((unsigned)(xA + 1) < 64u);
        const float* Mk = M + ((size_t)((b << 4) + k) << 12);

        // xp: rotation+translation sample of anchored part (window [iox,iox+16))
        float gxc = c * xn + tx;
        float gyc = s * xn + ty;
        int iox = 24 - sx, ioy = 24 - sy;
        float foxlo = (float)iox - 1.0f, foxhi = (float)iox + 16.0f;
        float foylo = (float)ioy - 1.0f, foyhi = (float)ioy + 16.0f;
        const float* pk = &sparts[k][0];

#pragma unroll
        for (int i = 0; i < 16; i++) {
            int h = hb + i;
            // --- KM sample (constant weights per (b,k), coalesced loads of M) ---
            int y0 = h + dy0, yA = y0 + sy;
            bool vy0 = ((unsigned)y0 < 64u) && ((unsigned)yA < 64u);
            bool vy1 = ((unsigned)(y0 + 1) < 64u) && ((unsigned)(yA + 1) < 64u);
            float m00 = 0.0f, m01 = 0.0f, m10 = 0.0f, m11 = 0.0f;
            if (vy0) {
                const float* r = Mk + yA * 64 + xA;
                if (vx0) m00 = r[0];
                if (vx1) m01 = r[1];
            }
            if (vy1) {
                const float* r = Mk + (yA + 1) * 64 + xA;
                if (vx0) m10 = r[0];
                if (vx1) m11 = r[1];
            }
            float r0 = m00 + wx * (m01 - m00);
            float r1 = m10 + wx * (m11 - m10);
            float km = r0 + wy * (r1 - r0);
            den[i] += km;

            // --- xp sample (skippable outside the rotated 17x17 window) ---
            float yn  = (2 * h + 1) * (1.0f / 64.0f) - 1.0f;
            float gx  = gxc - s * yn;
            float gy  = gyc + c * yn;
            float ppx = gx * 32.0f + 31.5f;
            float ppy = gy * 32.0f + 31.5f;
            if (ppx > foxlo && ppx < foxhi && ppy > foylo && ppy < foyhi) {
                float fjx = floorf(ppx), fjy = floorf(ppy);
                float ux = ppx - fjx, uy = ppy - fjy;
                int px0 = (int)fjx - iox, py0 = (int)fjy - ioy;
                float p00 = 0.0f, p01 = 0.0f, p10 = 0.0f, p11 = 0.0f;
                if ((unsigned)py0 < 16u) {
                    if ((unsigned)px0 < 16u)       p00 = pk[py0 * 16 + px0];
                    if ((unsigned)(px0 + 1) < 16u) p01 = pk[py0 * 16 + px0 + 1];
                }
                if ((unsigned)(py0 + 1) < 16u) {
                    if ((unsigned)px0 < 16u)       p10 = pk[(py0 + 1) * 16 + px0];
                    if ((unsigned)(px0 + 1) < 16u) p11 = pk[(py0 + 1) * 16 + px0 + 1];
                }
                float q0 = p00 + ux * (p01 - p00);
                float q1 = p10 + ux * (p11 - p10);
                float xp = q0 + uy * (q1 - q0);
                num[i] += xp * km;
            }
        }
    }

    float* xb = g_x + b * 4096 + w;
#pragma unroll
    for (int i = 0; i < 16; i++) {
        float d = den[i];
        d = (d == 0.0f) ? 1.0f : d;
        xb[(hb + i) * 64] = num[i] / d;
    }
}

// ---------------- 5) global transform: bilinear resample of composited image ----------------
__global__ __launch_bounds__(256) void global_kernel(float* __restrict__ out)
{
    int b = blockIdx.x, t = threadIdx.x;
    int w = t & 63;
    int h = blockIdx.y * 4 + (t >> 6);
    float4 gp = g_gpar[b];
    float xn = (2 * w + 1) * (1.0f / 64.0f) - 1.0f;
    float yn = (2 * h + 1) * (1.0f / 64.0f) - 1.0f;
    float gx = gp.x * xn - gp.y * yn + gp.z;
    float gy = gp.y * xn + gp.x * yn + gp.w;
    float px = fminf(fmaxf(gx * 32.0f + 31.5f, -8.0f), 72.0f);
    float py = fminf(fmaxf(gy * 32.0f + 31.5f, -8.0f), 72.0f);
    float fx0 = floorf(px), fy0 = floorf(py);
    float wx = px - fx0, wy = py - fy0;
    int x0 = (int)fx0, y0 = (int)fy0;
    const float* xb = g_x + b * 4096;
    float v00 = 0.0f, v01 = 0.0f, v10 = 0.0f, v11 = 0.0f;
    bool vx0 = (unsigned)x0 < 64u, vx1 = (unsigned)(x0 + 1) < 64u;
    bool vy0 = (unsigned)y0 < 64u, vy1 = (unsigned)(y0 + 1) < 64u;
    if (vx0 && vy0) v00 = xb[y0 * 64 + x0];
    if (vx1 && vy0) v01 = xb[y0 * 64 + x0 + 1];
    if (vx0 && vy1) v10 = xb[(y0 + 1) * 64 + x0];
    if (vx1 && vy1) v11 = xb[(y0 + 1) * 64 + x0 + 1];
    float r0 = v00 + wx * (v01 - v00);
    float r1 = v10 + wx * (v11 - v10);
    out[b * 4096 + h * 64 + w] = r0 + wy * (r1 - r0);
}

// ---------------- launch ----------------
extern "C" void kernel_launch(void* const* d_in, const int* in_sizes, int n_in,
                              void* d_out, int out_size)
{
    const float* inputs = (const float*)d_in[0];
    const float* W1     = (const float*)d_in[1];
    const float* b1     = (const float*)d_in[2];
    const float* W2     = (const float*)d_in[3];
    const float* b2     = (const float*)d_in[4];
    const float* Wum    = (const float*)d_in[5];
    const float* bum    = (const float*)d_in[6];
    const float* Wuv    = (const float*)d_in[7];
    const float* buv    = (const float*)d_in[8];
    const float* Wgm    = (const float*)d_in[9];
    const float* bgm    = (const float*)d_in[10];
    const float* Wgv    = (const float*)d_in[11];
    const float* bgv    = (const float*)d_in[12];
    const float* Wz     = (const float*)d_in[13];
    const float* M      = (const float*)d_in[14];
    const float* eps_u  = (const float*)d_in[15];
    const float* eps_g  = (const float*)d_in[16];
    float* out = (float*)d_out;

    float *hid1, *hid2;
    cudaGetSymbolAddress((void**)&hid1, g_hid1);
    cudaGetSymbolAddress((void**)&hid2, g_hid2);

    part_kernel<<<16, 256>>>(Wz);
    gemm_bias_relu<<<dim3(HDN / 64, BB / 32), 256>>>(inputs, W1, b1, hid1, BB, HDN, HWN, 1);
    gemm_bias_relu<<<dim3(HDN / 64, BB / 32), 256>>>(hid1, W2, b2, hid2, BB, HDN, HDN, 1);
    heads_kernel<<<BB / 2, 256>>>(Wum, bum, Wuv, buv, Wgm, bgm, Wgv, bgv, eps_u, eps_g);
    composite_kernel<<<BB, 256>>>(M);
    global_kernel<<<dim3(BB, 16), 256>>>(out);
}

// round 4
// speedup vs baseline: 1.6780x; 1.4080x over previous
#include <cuda_runtime.h>
#include <cuda_bf16.h>
#include <math.h>
#include <stdint.h>

#define BB 256
#define HDN 1024
#define HWN 4096
#define NP 16

// ================= helpers =================
__device__ __forceinline__ uint32_t smem_to_u32(const void* p) {
    uint32_t a;
    asm("{ .reg .u64 tmp; cvta.to.shared.u64 tmp, %1; cvt.u32.u64 %0, tmp; }" : "=r"(a) : "l"(p));
    return a;
}
#define CP16(dst, src) \
    asm volatile("cp.async.cg.shared.global [%0], [%1], 16;" :: "r"((uint32_t)(dst)), "l"(src))
#define CP_COMMIT() asm volatile("cp.async.commit_group;" ::: "memory")
#define CP_WAIT(n)  asm volatile("cp.async.wait_group %0;" :: "n"(n) : "memory")

__device__ __forceinline__ void ldmx4(uint32_t* r, uint32_t a) {
    asm volatile("ldmatrix.sync.aligned.m8n8.x4.shared.b16 {%0,%1,%2,%3}, [%4];"
        : "=r"(r[0]), "=r"(r[1]), "=r"(r[2]), "=r"(r[3]) : "r"(a));
}
__device__ __forceinline__ void mma_bf16(float* c, const uint32_t* a, const uint32_t* b) {
    asm volatile(
        "mma.sync.aligned.m16n8k16.row.col.f32.bf16.bf16.f32 "
        "{%0,%1,%2,%3}, {%4,%5,%6,%7}, {%8,%9}, {%0,%1,%2,%3};"
        : "+f"(c[0]), "+f"(c[1]), "+f"(c[2]), "+f"(c[3])
        : "r"(a[0]), "r"(a[1]), "r"(a[2]), "r"(a[3]), "r"(b[0]), "r"(b[1]));
}

static __device__ __forceinline__ uint32_t sw128(uint32_t off) { return off ^ ((off >> 3) & 0x70); }

__device__ __forceinline__ uint32_t split_pack(float v0, float v1, uint32_t& lopack) {
    __nv_bfloat16 h0 = __float2bfloat16(v0);
    __nv_bfloat16 h1 = __float2bfloat16(v1);
    __nv_bfloat16 l0 = __float2bfloat16(v0 - __bfloat162float(h0));
    __nv_bfloat16 l1 = __float2bfloat16(v1 - __bfloat162float(h1));
    lopack = ((uint32_t)__bfloat16_as_ushort(l1) << 16) | (uint32_t)__bfloat16_as_ushort(l0);
    return ((uint32_t)__bfloat16_as_ushort(h1) << 16) | (uint32_t)__bfloat16_as_ushort(h0);
}

// ================= scratch (device globals) =================
__device__ float  g_part[NP * 256];
__device__ float4 g_params[BB * NP];
__device__ float4 g_gpar[BB];
__device__ float  g_x[BB * 4096];
__device__ float  g_heads[BB * 128];
__device__ float  g_partial[4 * 256 * 1024];   // split-K partials (4 MB)

// pre-swizzled bf16 block buffers. A blocks: [mt][kc] 128x64 (16KB). B blocks: [nt][kc] 64x64 (8KB).
__device__ __align__(1024) __nv_bfloat16 g_A1h[2 * 64 * 8192];
__device__ __align__(1024) __nv_bfloat16 g_A1l[2 * 64 * 8192];
__device__ __align__(1024) __nv_bfloat16 g_A2h[2 * 16 * 8192];
__device__ __align__(1024) __nv_bfloat16 g_A2l[2 * 16 * 8192];
__device__ __align__(1024) __nv_bfloat16 g_A3h[2 * 16 * 8192];
__device__ __align__(1024) __nv_bfloat16 g_A3l[2 * 16 * 8192];
__device__ __align__(1024) __nv_bfloat16 g_W1h[16 * 64 * 4096];
__device__ __align__(1024) __nv_bfloat16 g_W1l[16 * 64 * 4096];
__device__ __align__(1024) __nv_bfloat16 g_W2h[16 * 16 * 4096];
__device__ __align__(1024) __nv_bfloat16 g_W2l[16 * 16 * 4096];
__device__ __align__(1024) __nv_bfloat16 g_WHh[2 * 16 * 4096];
__device__ __align__(1024) __nv_bfloat16 g_WHl[2 * 16 * 4096];

// ================= 1) part decode =================
__global__ __launch_bounds__(256) void part_kernel(const float* __restrict__ Wz) {
    int i = blockIdx.x * 256 + threadIdx.x;
    float s = 0.0f;
#pragma unroll
    for (int z = 0; z < 32; z++) s += Wz[z * 4096 + i];
    g_part[i] = 1.0f / (1.0f + expf(-s));
}

// ================= convert A (inputs) -> swizzled hi/lo blocks =================
__global__ __launch_bounds__(256) void convA_kernel(const float* __restrict__ A) {
    int kc = blockIdx.x, mt = blockIdx.y;
    int t = threadIdx.x;
    int ml = t >> 1;
    int half = (t & 1) * 32;
    const float* src = A + (size_t)(mt * 128 + ml) * HWN + kc * 64 + half;
    size_t blk = ((size_t)mt * 64 + kc) * 8192;
    char* dh = (char*)(g_A1h + blk);
    char* dl = (char*)(g_A1l + blk);
#pragma unroll
    for (int i = 0; i < 32; i += 2) {
        float v0 = src[i], v1 = src[i + 1];
        uint32_t lo, hi = split_pack(v0, v1, lo);
        uint32_t off = sw128((uint32_t)(ml * 128 + (half + i) * 2));
        *(uint32_t*)(dh + off) = hi;
        *(uint32_t*)(dl + off) = lo;
    }
}

// ================= convert + transpose weight W[K][N] -> B^T blocks [nt][kc] =================
__global__ __launch_bounds__(256) void convW_kernel(
    const float* __restrict__ W, int N, int KCH,
    __nv_bfloat16* __restrict__ outH, __nv_bfloat16* __restrict__ outL)
{
    __shared__ float s_tile[64][68];
    int nt = blockIdx.x, kc = blockIdx.y;
    int t = threadIdx.x;
    {
        int kr = t >> 2, q = (t & 3) * 16;
        const float* src = W + (size_t)(kc * 64 + kr) * N + nt * 64 + q;
#pragma unroll
        for (int i = 0; i < 16; i += 4) {
            float4 v = *(const float4*)(src + i);
            s_tile[kr][q + i + 0] = v.x; s_tile[kr][q + i + 1] = v.y;
            s_tile[kr][q + i + 2] = v.z; s_tile[kr][q + i + 3] = v.w;
        }
    }
    __syncthreads();
    {
        int nl = t >> 2, kq = (t & 3) * 16;
        size_t blk = ((size_t)nt * KCH + kc) * 4096;
        char* dh = (char*)(outH + blk);
        char* dl = (char*)(outL + blk);
#pragma unroll
        for (int i = 0; i < 16; i += 2) {
            float v0 = s_tile[kq + i][nl], v1 = s_tile[kq + i + 1][nl];
            uint32_t lo, hi = split_pack(v0, v1, lo);
            uint32_t off = sw128((uint32_t)(nl * 128 + (kq + i) * 2));
            *(uint32_t*)(dh + off) = hi;
            *(uint32_t*)(dl + off) = lo;
        }
    }
}

// ================= heads weight pack: 128 N-cols from Wum/Wuv/Wgm/Wgv =================
__global__ __launch_bounds__(256) void convWH_kernel(
    const float* __restrict__ Wum, const float* __restrict__ Wuv,
    const float* __restrict__ Wgm, const float* __restrict__ Wgv)
{
    int nt = blockIdx.x, kc = blockIdx.y;
    int t = threadIdx.x;
    int nl = t >> 2, kq = (t & 3) * 16;
    int j = nt * 64 + nl;
    size_t blk = ((size_t)nt * 16 + kc) * 4096;
    char* dh = (char*)(g_WHh + blk);
    char* dl = (char*)(g_WHl + blk);
#pragma unroll 2
    for (int i = 0; i < 16; i += 2) {
        float v0 = 0.0f, v1 = 0.0f;
        int k0 = kc * 64 + kq + i;
#pragma unroll
        for (int e = 0; e < 2; e++) {
            int k = k0 + e;
            float v = 0.0f;
            if (j < 48)       v = Wum[k * 48 + j];
            else if (j < 96)  v = Wuv[k * 48 + (j - 48)];
            else if (j < 99)  v = Wgm[k * 3 + (j - 96)];
            else if (j < 102) v = Wgv[k * 3 + (j - 99)];
            if (e == 0) v0 = v; else v1 = v;
        }
        uint32_t lo, hi = split_pack(v0, v1, lo);
        uint32_t off = sw128((uint32_t)(nl * 128 + (kq + i) * 2));
        *(uint32_t*)(dh + off) = hi;
        *(uint32_t*)(dl + off) = lo;
    }
}

// ================= mma.sync bf16-split GEMM =================
// CTA tile 128(M) x 64(N), split-K over blockIdx.z, KBLK k64-chunks per CTA.
// D = Ah*Bh + Ah*Bl + Al*Bh (fp32 accum) -> partial[ks][256][N]
// smem stage: Ah 16K | Al 16K | Bh 8K | Bl 8K = 48KB, double buffered.
template <int KBLK>
__global__ __launch_bounds__(256, 1) void mma_gemm(
    const __nv_bfloat16* __restrict__ Ah, const __nv_bfloat16* __restrict__ Al,
    const __nv_bfloat16* __restrict__ Bh, const __nv_bfloat16* __restrict__ Bl,
    float* __restrict__ partial, int KCH, int N)
{
    extern __shared__ char smem[];
    uint32_t sb = smem_to_u32(smem);
    int t = threadIdx.x, wid = t >> 5, l = t & 31;
    int nt = blockIdx.x, mt = blockIdx.y, ks = blockIdx.z;
    int kc0 = ks * KBLK;

    const char* pAh = (const char*)Ah + ((size_t)mt * KCH + kc0) * 16384;
    const char* pAl = (const char*)Al + ((size_t)mt * KCH + kc0) * 16384;
    const char* pBh = (const char*)Bh + ((size_t)nt * KCH + kc0) * 8192;
    const char* pBl = (const char*)Bl + ((size_t)nt * KCH + kc0) * 8192;

    int m0 = (wid >> 1) * 32, n0 = (wid & 1) * 32;
    float acc[2][4][4];
#pragma unroll
    for (int a = 0; a < 2; a++)
#pragma unroll
        for (int b = 0; b < 4; b++)
#pragma unroll
            for (int c = 0; c < 4; c++) acc[a][b][c] = 0.0f;

    // ldmatrix per-lane row offsets (bytes) + swizzle xor
    uint32_t aRow = (uint32_t)(m0 + (l & 7) + ((l >> 3) & 1) * 8) * 128;
    uint32_t bRow = (uint32_t)(n0 + (l & 7) + ((l >> 4) & 1) * 8) * 128;
    uint32_t kaddA2 = ((l >> 4) & 1) * 16;   // byte offset of k-half for A
    uint32_t kaddB2 = ((l >> 3) & 1) * 16;   // byte offset of k-half for B
    uint32_t xr = (uint32_t)(l & 7) << 4;

    // stage 0 load
    {
        uint32_t d = sb;
#pragma unroll
        for (int i = 0; i < 4; i++) CP16(d + (t + i * 256) * 16, pAh + (t + i * 256) * 16);
#pragma unroll
        for (int i = 0; i < 4; i++) CP16(d + 16384 + (t + i * 256) * 16, pAl + (t + i * 256) * 16);
#pragma unroll
        for (int i = 0; i < 2; i++) CP16(d + 32768 + (t + i * 256) * 16, pBh + (t + i * 256) * 16);
#pragma unroll
        for (int i = 0; i < 2; i++) CP16(d + 40960 + (t + i * 256) * 16, pBl + (t + i * 256) * 16);
        CP_COMMIT();
    }

#pragma unroll 1
    for (int c = 0; c < KBLK; c++) {
        if (c + 1 < KBLK) {
            uint32_t d = sb + ((c + 1) & 1) * 49152;
            size_t co = (size_t)(c + 1);
#pragma unroll
            for (int i = 0; i < 4; i++) CP16(d + (t + i * 256) * 16, pAh + co * 16384 + (t + i * 256) * 16);
#pragma unroll
            for (int i = 0; i < 4; i++) CP16(d + 16384 + (t + i * 256) * 16, pAl + co * 16384 + (t + i * 256) * 16);
#pragma unroll
            for (int i = 0; i < 2; i++) CP16(d + 32768 + (t + i * 256) * 16, pBh + co * 8192 + (t + i * 256) * 16);
#pragma unroll
            for (int i = 0; i < 2; i++) CP16(d + 40960 + (t + i * 256) * 16, pBl + co * 8192 + (t + i * 256) * 16);
            CP_COMMIT();
            CP_WAIT(1);
        } else {
            CP_WAIT(0);
        }
        __syncthreads();

        uint32_t st = sb + (c & 1) * 49152;
#pragma unroll
        for (int ko2 = 0; ko2 < 128; ko2 += 32) {   // 4 k16 steps (byte-scaled)
            uint32_t xA = (ko2 + kaddA2) ^ xr;
            uint32_t xB = (ko2 + kaddB2) ^ xr;
            uint32_t aH0[4], aH1[4], aL0[4], aL1[4], bH[8], bL[8];
            ldmx4(aH0, st + aRow + xA);
            ldmx4(aH1, st + aRow + 2048 + xA);
            ldmx4(aL0, st + 16384 + aRow + xA);
            ldmx4(aL1, st + 16384 + aRow + 2048 + xA);
            ldmx4(bH,     st + 32768 + bRow + xB);
            ldmx4(bH + 4, st + 32768 + bRow + 2048 + xB);
            ldmx4(bL,     st + 40960 + bRow + xB);
            ldmx4(bL + 4, st + 40960 + bRow + 2048 + xB);
#pragma unroll
            for (int mf = 0; mf < 2; mf++) {
                const uint32_t* ah = mf ? aH1 : aH0;
                const uint32_t* al = mf ? aL1 : aL0;
#pragma unroll
                for (int nf = 0; nf < 4; nf++) {
                    mma_bf16(acc[mf][nf], ah, bH + nf * 2);
                    mma_bf16(acc[mf][nf], ah, bL + nf * 2);
                    mma_bf16(acc[mf][nf], al, bH + nf * 2);
                }
            }
        }
        __syncthreads();
    }

    // epilogue: write fp32 partial tile
    int g = l >> 2, tg = l & 3;
#pragma unroll
    for (int mf = 0; mf < 2; mf++) {
#pragma unroll
        for (int nf = 0; nf < 4; nf++) {
            int gm = mt * 128 + m0 + mf * 16 + g;
            int gn = nt * 64 + n0 + nf * 8 + tg * 2;
            float* dst = partial + (size_t)ks * 256 * N + (size_t)gm * N + gn;
            float2 v0 = make_float2(acc[mf][nf][0], acc[mf][nf][1]);
            float2 v1 = make_float2(acc[mf][nf][2], acc[mf][nf][3]);
            *(float2*)dst = v0;
            *(float2*)(dst + (size_t)8 * N) = v1;
        }
    }
}

// ================= epilogue: reduce split-K + bias + relu + pack to blocks =================
__global__ __launch_bounds__(256) void epi_pack(
    const float* __restrict__ partial, const float* __restrict__ bias,
    __nv_bfloat16* __restrict__ outH, __nv_bfloat16* __restrict__ outL)
{
    int nt = blockIdx.x, mt = blockIdx.y;
    int t = threadIdx.x;
    int ml = t >> 1;
    int half = (t & 1) * 32;
    int row = mt * 128 + ml;
    int col0 = nt * 64 + half;
    const float* p = partial + (size_t)row * 1024 + col0;
    size_t blk = ((size_t)mt * gridDim.x + nt) * 8192;
    char* dh = (char*)(outH + blk);
    char* dl = (char*)(outL + blk);
#pragma unroll 4
    for (int i = 0; i < 32; i += 2) {
        float v0 = p[i]     + p[i + 262144]     + p[i + 524288]     + p[i + 786432];
        float v1 = p[i + 1] + p[i + 1 + 262144] + p[i + 1 + 524288] + p[i + 1 + 786432];
        v0 = fmaxf(v0 + bias[col0 + i], 0.0f);
        v1 = fmaxf(v1 + bias[col0 + i + 1], 0.0f);
        uint32_t lo, hi = split_pack(v0, v1, lo);
        uint32_t off = sw128((uint32_t)(ml * 128 + (half + i) * 2));
        *(uint32_t*)(dh + off) = hi;
        *(uint32_t*)(dl + off) = lo;
    }
}

// ================= epilogue for heads gemm: reduce split-K to fp32 =================
__global__ __launch_bounds__(1024) void epi_heads(const float* __restrict__ partial)
{
    int idx = blockIdx.x * 1024 + threadIdx.x;   // 0..32767
    float s = partial[idx] + partial[idx + 32768] + partial[idx + 65536] + partial[idx + 98304];
    g_heads[idx] = s;
}

// ================= heads epilogue: activations + rot/trans params =================
__global__ __launch_bounds__(64) void heads_epi(
    const float* __restrict__ bum, const float* __restrict__ buv,
    const float* __restrict__ bgm, const float* __restrict__ bgv,
    const float* __restrict__ eps_u, const float* __restrict__ eps_g)
{
    __shared__ float su[48];
    __shared__ float sg[3];
    int b = blockIdx.x, t = threadIdx.x;
    const float* hr = g_heads + (size_t)b * 128;
    if (t < 48) {
        float umu  = tanhf(hr[t] + bum[t]);
        float up   = hr[48 + t] + buv[t];
        float uvar = expf(up > -6.0f ? up : -6.0f);        // threshold(x,-6,-6)
        su[t] = umu + uvar * eps_u[b * 48 + t];
    } else if (t < 51) {
        int j = t - 48;
        float gmu  = tanhf(hr[96 + j] + bgm[j]);
        float gp   = hr[99 + j] + bgv[j];
        float gvar = expf(gp > -6.0f ? gp : 6.0f);         // threshold(x,-6,6) !
        sg[j] = gmu + gvar * eps_g[b * 3 + j];
    }
    __syncthreads();
    if (t < 16) {
        float a = su[3 * t], tx = su[3 * t + 1], ty = su[3 * t + 2];
        g_params[b * 16 + t] = make_float4(cosf(a), sinf(a), tx, ty);
    } else if (t == 16) {
        g_gpar[b] = make_float4(cosf(sg[0]), sinf(sg[0]), sg[1], sg[2]);
    }
}

// ================= fused composite (unchanged, proven) =================
__global__ __launch_bounds__(256) void composite_kernel(const float* __restrict__ M)
{
    __shared__ float  sparts[NP][256];
    __shared__ float4 spar[NP];
    int b = blockIdx.x, t = threadIdx.x;
    for (int i = t; i < NP * 256; i += 256) sparts[i >> 8][i & 255] = g_part[i];
    if (t < 16) spar[t] = g_params[b * 16 + t];
    __syncthreads();

    int w  = t & 63;
    int hb = (t >> 6) * 16;
    float num[16], den[16];
#pragma unroll
    for (int i = 0; i < 16; i++) { num[i] = 0.0f; den[i] = 0.0f; }
    float xn = (2 * w + 1) * (1.0f / 64.0f) - 1.0f;

#pragma unroll 1
    for (int k = 0; k < 16; k++) {
        float4 pp = spar[k];
        float c = pp.x, s = pp.y, tx = pp.z, ty = pp.w;
        int sx = (k & 3) * 8 - 12;
        int sy = (k >> 2) * 8 - 12;

        float fx = fminf(fmaxf(tx * 32.0f, -1e8f), 1e8f);
        float fy = fminf(fmaxf(ty * 32.0f, -1e8f), 1e8f);
        float ffx = floorf(fx), ffy = floorf(fy);
        float wx = fx - ffx, wy = fy - ffy;
        int dx0 = (int)ffx, dy0 = (int)ffy;
        int x0 = w + dx0, xA = x0 + sx;
        bool vx0 = ((unsigned)x0 < 64u) && ((unsigned)xA < 64u);
        bool vx1 = ((unsigned)(x0 + 1) < 64u) && ((unsigned)(xA + 1) < 64u);
        const float* Mk = M + ((size_t)((b << 4) + k) << 12);

        float gxc = c * xn + tx;
        float gyc = s * xn + ty;
        int iox = 24 - sx, ioy = 24 - sy;
        float foxlo = (float)iox - 1.0f, foxhi = (float)iox + 16.0f;
        float foylo = (float)ioy - 1.0f, foyhi = (float)ioy + 16.0f;
        const float* pk = &sparts[k][0];

#pragma unroll
        for (int i = 0; i < 16; i++) {
            int h = hb + i;
            int y0 = h + dy0, yA = y0 + sy;
            bool vy0 = ((unsigned)y0 < 64u) && ((unsigned)yA < 64u);
            bool vy1 = ((unsigned)(y0 + 1) < 64u) && ((unsigned)(yA + 1) < 64u);
            float m00 = 0.0f, m01 = 0.0f, m10 = 0.0f, m11 = 0.0f;
            if (vy0) {
                const float* r = Mk + yA * 64 + xA;
                if (vx0) m00 = r[0];
                if (vx1) m01 = r[1];
            }
            if (vy1) {
                const float* r = Mk + (yA + 1) * 64 + xA;
                if (vx0) m10 = r[0];
                if (vx1) m11 = r[1];
            }
            float r0 = m00 + wx * (m01 - m00);
            float r1 = m10 + wx * (m11 - m10);
            float km = r0 + wy * (r1 - r0);
            den[i] += km;

            float yn  = (2 * h + 1) * (1.0f / 64.0f) - 1.0f;
            float gx  = gxc - s * yn;
            float gy  = gyc + c * yn;
            float ppx = gx * 32.0f + 31.5f;
            float ppy = gy * 32.0f + 31.5f;
            if (ppx > foxlo && ppx < foxhi && ppy > foylo && ppy < foyhi) {
                float fjx = floorf(ppx), fjy = floorf(ppy);
                float ux = ppx - fjx, uy = ppy - fjy;
                int px0 = (int)fjx - iox, py0 = (int)fjy - ioy;
                float p00 = 0.0f, p01 = 0.0f, p10 = 0.0f, p11 = 0.0f;
                if ((unsigned)py0 < 16u) {
                    if ((unsigned)px0 < 16u)       p00 = pk[py0 * 16 + px0];
                    if ((unsigned)(px0 + 1) < 16u) p01 = pk[py0 * 16 + px0 + 1];
                }
                if ((unsigned)(py0 + 1) < 16u) {
                    if ((unsigned)px0 < 16u)       p10 = pk[(py0 + 1) * 16 + px0];
                    if ((unsigned)(px0 + 1) < 16u) p11 = pk[(py0 + 1) * 16 + px0 + 1];
                }
                float q0 = p00 + ux * (p01 - p00);
                float q1 = p10 + ux * (p11 - p10);
                float xp = q0 + uy * (q1 - q0);
                num[i] += xp * km;
            }
        }
    }

    float* xb = g_x + b * 4096 + w;
#pragma unroll
    for (int i = 0; i < 16; i++) {
        float d = den[i];
        d = (d == 0.0f) ? 1.0f : d;
        xb[(hb + i) * 64] = num[i] / d;
    }
}

// ================= global transform (unchanged) =================
__global__ __launch_bounds__(256) void global_kernel(float* __restrict__ out)
{
    int b = blockIdx.x, t = threadIdx.x;
    int w = t & 63;
    int h = blockIdx.y * 4 + (t >> 6);
    float4 gp = g_gpar[b];
    float xn = (2 * w + 1) * (1.0f / 64.0f) - 1.0f;
    float yn = (2 * h + 1) * (1.0f / 64.0f) - 1.0f;
    float gx = gp.x * xn - gp.y * yn + gp.z;
    float gy = gp.y * xn + gp.x * yn + gp.w;
    float px = fminf(fmaxf(gx * 32.0f + 31.5f, -8.0f), 72.0f);
    float py = fminf(fmaxf(gy * 32.0f + 31.5f, -8.0f), 72.0f);
    float fx0 = floorf(px), fy0 = floorf(py);
    float wx = px - fx0, wy = py - fy0;
    int x0 = (int)fx0, y0 = (int)fy0;
    const float* xb = g_x + b * 4096;
    float v00 = 0.0f, v01 = 0.0f, v10 = 0.0f, v11 = 0.0f;
    bool vx0 = (unsigned)x0 < 64u, vx1 = (unsigned)(x0 + 1) < 64u;
    bool vy0 = (unsigned)y0 < 64u, vy1 = (unsigned)(y0 + 1) < 64u;
    if (vx0 && vy0) v00 = xb[y0 * 64 + x0];
    if (vx1 && vy0) v01 = xb[y0 * 64 + x0 + 1];
    if (vx0 && vy1) v10 = xb[(y0 + 1) * 64 + x0];
    if (vx1 && vy1) v11 = xb[(y0 + 1) * 64 + x0 + 1];
    float r0 = v00 + wx * (v01 - v00);
    float r1 = v10 + wx * (v11 - v10);
    out[b * 4096 + h * 64 + w] = r0 + wy * (r1 - r0);
}

// ================= launch =================
extern "C" void kernel_launch(void* const* d_in, const int* in_sizes, int n_in,
                              void* d_out, int out_size)
{
    const float* inputs = (const float*)d_in[0];
    const float* W1     = (const float*)d_in[1];
    const float* b1     = (const float*)d_in[2];
    const float* W2     = (const float*)d_in[3];
    const float* b2     = (const float*)d_in[4];
    const float* Wum    = (const float*)d_in[5];
    const float* bum    = (const float*)d_in[6];
    const float* Wuv    = (const float*)d_in[7];
    const float* buv    = (const float*)d_in[8];
    const float* Wgm    = (const float*)d_in[9];
    const float* bgm    = (const float*)d_in[10];
    const float* Wgv    = (const float*)d_in[11];
    const float* bgv    = (const float*)d_in[12];
    const float* Wz     = (const float*)d_in[13];
    const float* M      = (const float*)d_in[14];
    const float* eps_u  = (const float*)d_in[15];
    const float* eps_g  = (const float*)d_in[16];
    float* out = (float*)d_out;

    const int SMEM_DYN = 2 * 49152;
    cudaFuncSetAttribute(mma_gemm<16>, cudaFuncAttributeMaxDynamicSharedMemorySize, SMEM_DYN);
    cudaFuncSetAttribute(mma_gemm<4>,  cudaFuncAttributeMaxDynamicSharedMemorySize, SMEM_DYN);

    __nv_bfloat16 *A1h, *A1l, *A2h, *A2l, *A3h, *A3l, *W1h, *W1l, *W2h, *W2l, *WHh, *WHl;
    float* partial;
    cudaGetSymbolAddress((void**)&A1h, g_A1h); cudaGetSymbolAddress((void**)&A1l, g_A1l);
    cudaGetSymbolAddress((void**)&A2h, g_A2h); cudaGetSymbolAddress((void**)&A2l, g_A2l);
    cudaGetSymbolAddress((void**)&A3h, g_A3h); cudaGetSymbolAddress((void**)&A3l, g_A3l);
    cudaGetSymbolAddress((void**)&W1h, g_W1h); cudaGetSymbolAddress((void**)&W1l, g_W1l);
    cudaGetSymbolAddress((void**)&W2h, g_W2h); cudaGetSymbolAddress((void**)&W2l, g_W2l);
    cudaGetSymbolAddress((void**)&WHh, g_WHh); cudaGetSymbolAddress((void**)&WHl, g_WHl);
    cudaGetSymbolAddress((void**)&partial, g_partial);

    part_kernel<<<16, 256>>>(Wz);
    convA_kernel<<<dim3(64, 2), 256>>>(inputs);
    convW_kernel<<<dim3(16, 64), 256>>>(W1, 1024, 64, W1h, W1l);
    convW_kernel<<<dim3(16, 16), 256>>>(W2, 1024, 16, W2h, W2l);
    convWH_kernel<<<dim3(2, 16), 256>>>(Wum, Wuv, Wgm, Wgv);

    // GEMM1: [256x4096] x [4096x1024], split-K 4
    mma_gemm<16><<<dim3(16, 2, 4), 256, SMEM_DYN>>>(A1h, A1l, W1h, W1l, partial, 64, 1024);
    epi_pack<<<dim3(16, 2), 256>>>(partial, b1, A2h, A2l);
    // GEMM2: [256x1024] x [1024x1024], split-K 4
    mma_gemm<4><<<dim3(16, 2, 4), 256, SMEM_DYN>>>(A2h, A2l, W2h, W2l, partial, 16, 1024);
    epi_pack<<<dim3(16, 2), 256>>>(partial, b2, A3h, A3l);
    // GEMM3 (heads): [256x1024] x [1024x128], split-K 4
    mma_gemm<4><<<dim3(2, 2, 4), 256, SMEM_DYN>>>(A3h, A3l, WHh, WHl, partial, 16, 128);
    epi_heads<<<32, 1024>>>(partial);

    heads_epi<<<BB, 64>>>(bum, buv, bgm, bgv, eps_u, eps_g);
    composite_kernel<<<BB, 256>>>(M);
    global_kernel<<<dim3(BB, 16), 256>>>(out);
}

// round 5
// speedup vs baseline: 2.2912x; 1.3654x over previous
#include <cuda_runtime.h>
#include <cuda_bf16.h>
#include <math.h>
#include <stdint.h>

#define BB 256
#define HDN 1024
#define HWN 4096
#define NP 16

// ================= helpers =================
__device__ __forceinline__ uint32_t smem_to_u32(const void* p) {
    uint32_t a;
    asm("{ .reg .u64 tmp; cvta.to.shared.u64 tmp, %1; cvt.u32.u64 %0, tmp; }" : "=r"(a) : "l"(p));
    return a;
}
#define CP16(dst, src) \
    asm volatile("cp.async.cg.shared.global [%0], [%1], 16;" :: "r"((uint32_t)(dst)), "l"(src))
#define CP_COMMIT() asm volatile("cp.async.commit_group;" ::: "memory")
#define CP_WAIT(n)  asm volatile("cp.async.wait_group %0;" :: "n"(n) : "memory")

__device__ __forceinline__ void ldmx4(uint32_t* r, uint32_t a) {
    asm volatile("ldmatrix.sync.aligned.m8n8.x4.shared.b16 {%0,%1,%2,%3}, [%4];"
        : "=r"(r[0]), "=r"(r[1]), "=r"(r[2]), "=r"(r[3]) : "r"(a));
}
__device__ __forceinline__ void ldmx4t(uint32_t* r, uint32_t a) {
    asm volatile("ldmatrix.sync.aligned.m8n8.x4.trans.shared.b16 {%0,%1,%2,%3}, [%4];"
        : "=r"(r[0]), "=r"(r[1]), "=r"(r[2]), "=r"(r[3]) : "r"(a));
}
__device__ __forceinline__ void mma_bf16(float* c, const uint32_t* a, const uint32_t* b) {
    asm volatile(
        "mma.sync.aligned.m16n8k16.row.col.f32.bf16.bf16.f32 "
        "{%0,%1,%2,%3}, {%4,%5,%6,%7}, {%8,%9}, {%0,%1,%2,%3};"
        : "+f"(c[0]), "+f"(c[1]), "+f"(c[2]), "+f"(c[3])
        : "r"(a[0]), "r"(a[1]), "r"(a[2]), "r"(a[3]), "r"(b[0]), "r"(b[1]));
}

static __device__ __forceinline__ uint32_t sw128(uint32_t off) { return off ^ ((off >> 3) & 0x70); }

__device__ __forceinline__ uint32_t split_pack(float v0, float v1, uint32_t& lopack) {
    __nv_bfloat16 h0 = __float2bfloat16(v0);
    __nv_bfloat16 h1 = __float2bfloat16(v1);
    __nv_bfloat16 l0 = __float2bfloat16(v0 - __bfloat162float(h0));
    __nv_bfloat16 l1 = __float2bfloat16(v1 - __bfloat162float(h1));
    lopack = ((uint32_t)__bfloat16_as_ushort(l1) << 16) | (uint32_t)__bfloat16_as_ushort(l0);
    return ((uint32_t)__bfloat16_as_ushort(h1) << 16) | (uint32_t)__bfloat16_as_ushort(h0);
}

// ================= scratch (device globals) =================
__device__ float  g_part[NP * 256];
__device__ float4 g_params[BB * NP];
__device__ float4 g_gpar[BB];
__device__ float  g_heads[BB * 128];
__device__ float  g_partial[4 * 256 * 1024];   // split-K partials (4 MB)

// A blocks: [mt][kc] 128 rows x 64 k bf16, SW128 swizzled, 16KB. (m-major rows, k-contig)
__device__ __align__(1024) __nv_bfloat16 g_A1h[2 * 64 * 8192];
__device__ __align__(1024) __nv_bfloat16 g_A1l[2 * 64 * 8192];
__device__ __align__(1024) __nv_bfloat16 g_A2h[2 * 16 * 8192];
__device__ __align__(1024) __nv_bfloat16 g_A2l[2 * 16 * 8192];
__device__ __align__(1024) __nv_bfloat16 g_A3h[2 * 16 * 8192];
__device__ __align__(1024) __nv_bfloat16 g_A3l[2 * 16 * 8192];
// heads weights, K-MAJOR blocks: [nt][kc] 64 k-rows x 64 n bf16, SW128, 8KB
__device__ __align__(1024) __nv_bfloat16 g_WHh[2 * 16 * 4096];
__device__ __align__(1024) __nv_bfloat16 g_WHl[2 * 16 * 4096];

// ================= 1) part decode =================
__global__ __launch_bounds__(256) void part_kernel(const float* __restrict__ Wz) {
    int i = blockIdx.x * 256 + threadIdx.x;
    float s = 0.0f;
#pragma unroll
    for (int z = 0; z < 32; z++) s += Wz[z * 4096 + i];
    g_part[i] = 1.0f / (1.0f + expf(-s));
}

// ================= convert A (inputs) -> swizzled hi/lo blocks =================
__global__ __launch_bounds__(256) void convA_kernel(const float* __restrict__ A) {
    int kc = blockIdx.x, mt = blockIdx.y;
    int t = threadIdx.x;
    int ml = t >> 1;
    int half = (t & 1) * 32;
    const float* src = A + (size_t)(mt * 128 + ml) * HWN + kc * 64 + half;
    size_t blk = ((size_t)mt * 64 + kc) * 8192;
    char* dh = (char*)(g_A1h + blk);
    char* dl = (char*)(g_A1l + blk);
#pragma unroll
    for (int i = 0; i < 32; i += 2) {
        float v0 = src[i], v1 = src[i + 1];
        uint32_t lo, hi = split_pack(v0, v1, lo);
        uint32_t off = sw128((uint32_t)(ml * 128 + (half + i) * 2));
        *(uint32_t*)(dh + off) = hi;
        *(uint32_t*)(dl + off) = lo;
    }
}

// ================= heads weight pack -> K-MAJOR swizzled blocks =================
// grid (nt=2, kc=16), 256 threads.
__global__ __launch_bounds__(256) void convWH_kernel(
    const float* __restrict__ Wum, const float* __restrict__ Wuv,
    const float* __restrict__ Wgm, const float* __restrict__ Wgv)
{
    int nt = blockIdx.x, kc = blockIdx.y;
    int t = threadIdx.x;
    int kl = t >> 2;              // k row within chunk 0..63
    int nq = (t & 3) * 16;        // n segment
    int k = kc * 64 + kl;
    size_t blk = ((size_t)nt * 16 + kc) * 4096;
    char* dh = (char*)(g_WHh + blk);
    char* dl = (char*)(g_WHl + blk);
#pragma unroll 2
    for (int n2 = 0; n2 < 16; n2 += 2) {
        int nl = nq + n2;
        float vv[2];
#pragma unroll
        for (int e = 0; e < 2; e++) {
            int j = nt * 64 + nl + e;
            float v = 0.0f;
            if (j < 48)       v = Wum[k * 48 + j];
            else if (j < 96)  v = Wuv[k * 48 + (j - 48)];
            else if (j < 99)  v = Wgm[k * 3 + (j - 96)];
            else if (j < 102) v = Wgv[k * 3 + (j - 99)];
            vv[e] = v;
        }
        uint32_t lo, hi = split_pack(vv[0], vv[1], lo);
        uint32_t off = (uint32_t)kl * 128 + (((uint32_t)nl * 2) ^ (((uint32_t)kl & 7) << 4));
        *(uint32_t*)(dh + off) = hi;
        *(uint32_t*)(dl + off) = lo;
    }
}

// ================= mma.sync bf16-split GEMM, fused W conversion =================
// CTA tile 128(M) x 64(N); split-K over blockIdx.z; KBLK k64 chunks per CTA.
// D = Ah*Bh + Ah*Bl + Al*Bh (fp32) -> partial[ks][256][N]
// FUSE: B loaded as raw fp32 W tiles [k][n] and converted in-kernel to bf16 hi/lo.
// SMEM: stageA(s) = s*32768 {Ah 16K | Al 16K}; stageB(s) = 65536 + s*16384 {Bh 8K | Bl 8K};
//       raw(s) = 98304 + s*16384 (fp32 W tile, FUSE only). Total 128KB.
template <int KBLK, bool FUSE>
__global__ __launch_bounds__(256, 1) void mma_gemm(
    const __nv_bfloat16* __restrict__ Ah, const __nv_bfloat16* __restrict__ Al,
    const __nv_bfloat16* __restrict__ Bh, const __nv_bfloat16* __restrict__ Bl,
    const float* __restrict__ Wraw, int ldW,
    float* __restrict__ partial, int KCH, int N)
{
    extern __shared__ char smem[];
    uint32_t sb = smem_to_u32(smem);
    int t = threadIdx.x, wid = t >> 5, l = t & 31;
    int nt = blockIdx.x, mt = blockIdx.y, ks = blockIdx.z;
    int kc0 = ks * KBLK;
    int ncol0 = nt * 64;

    const char* pAh = (const char*)Ah + ((size_t)mt * KCH + kc0) * 16384;
    const char* pAl = (const char*)Al + ((size_t)mt * KCH + kc0) * 16384;
    const char* pBh = (const char*)Bh + ((size_t)nt * KCH + kc0) * 8192;
    const char* pBl = (const char*)Bl + ((size_t)nt * KCH + kc0) * 8192;

    int m0 = (wid >> 1) * 32, n0 = (wid & 1) * 32;
    float acc[2][4][4];
#pragma unroll
    for (int a = 0; a < 2; a++)
#pragma unroll
        for (int b = 0; b < 4; b++)
#pragma unroll
            for (int c = 0; c < 4; c++) acc[a][b][c] = 0.0f;

    uint32_t xr = (uint32_t)(l & 7) << 4;
    // A (row-major m x k): rows for mats 0/1 = m0..15; lanes16+ take k+8 (16B)
    uint32_t aRow   = (uint32_t)(m0 + (l & 7) + ((l >> 3) & 1) * 8) * 128;
    uint32_t kaddA2 = ((l >> 4) & 1) * 16;
    // B (K-major k x n, ldmatrix.trans): k rows: mats 0/2 = k0-7, 1/3 = k8-15; mats 2/3 at n+8
    uint32_t bRowB = (uint32_t)((l & 7) + ((l >> 3) & 1) * 8) * 128;
    uint32_t nb0   = (uint32_t)(n0 + ((l >> 4) & 1) * 8) * 2;
    uint32_t xB1 = nb0 ^ xr;
    uint32_t xB2 = (nb0 + 32) ^ xr;

    // conversion thread mapping (FUSE): raw [64 rows x 256B fp32] -> Bh/Bl swizzled
    int ckl = t >> 2;             // k row
    int csg = (t & 3) * 16;       // n segment (elements)
    int wrow = t & 63, wpart = t >> 6;   // raw cp.async mapping

    // ---- load issue helpers ----
    auto issue = [&](int chunk) {
        uint32_t sA = sb + (uint32_t)(chunk & 1) * 32768;
        const char* sah = pAh + (size_t)chunk * 16384;
        const char* sal = pAl + (size_t)chunk * 16384;
#pragma unroll
        for (int i = 0; i < 4; i++) CP16(sA + (t + i * 256) * 16, sah + (t + i * 256) * 16);
#pragma unroll
        for (int i = 0; i < 4; i++) CP16(sA + 16384 + (t + i * 256) * 16, sal + (t + i * 256) * 16);
        if (FUSE) {
            uint32_t sR = sb + 98304 + (uint32_t)(chunk & 1) * 16384;
            const char* sw = (const char*)Wraw +
                ((size_t)((kc0 + chunk) * 64 + wrow) * ldW + ncol0) * 4 + wpart * 64;
#pragma unroll
            for (int i = 0; i < 4; i++) CP16(sR + wrow * 256 + wpart * 64 + i * 16, sw + i * 16);
        } else {
            uint32_t sB = sb + 65536 + (uint32_t)(chunk & 1) * 16384;
            const char* sbh = pBh + (size_t)chunk * 8192;
            const char* sbl = pBl + (size_t)chunk * 8192;
#pragma unroll
            for (int i = 0; i < 2; i++) CP16(sB + (t + i * 256) * 16, sbh + (t + i * 256) * 16);
#pragma unroll
            for (int i = 0; i < 2; i++) CP16(sB + 8192 + (t + i * 256) * 16, sbl + (t + i * 256) * 16);
        }
        CP_COMMIT();
    };

    issue(0);

#pragma unroll 1
    for (int c = 0; c < KBLK; c++) {
        if (c + 1 < KBLK) { issue(c + 1); CP_WAIT(1); }
        else              { CP_WAIT(0); }
        __syncthreads();

        uint32_t stBh = sb + 65536 + (uint32_t)(c & 1) * 16384;
        uint32_t stBl = stBh + 8192;

        if (FUSE) {
            // convert raw fp32 [64x64] -> swizzled bf16 hi/lo (K-major)
            char* rawp = smem + 98304 + (c & 1) * 16384;
            char* dhp  = smem + 65536 + (c & 1) * 16384;
            char* dlp  = dhp + 8192;
            const float4* srcv = (const float4*)(rawp + ckl * 256 + csg * 4);
            uint32_t rowoff = (uint32_t)ckl * 128;
            uint32_t kx = ((uint32_t)ckl & 7) << 4;
#pragma unroll
            for (int q = 0; q < 4; q++) {
                float4 v = srcv[q];
                uint32_t lo0, hi0 = split_pack(v.x, v.y, lo0);
                uint32_t lo1, hi1 = split_pack(v.z, v.w, lo1);
                uint32_t off = rowoff + ((((uint32_t)(csg + q * 4)) * 2) ^ kx);
                *(uint2*)(dhp + off) = make_uint2(hi0, hi1);
                *(uint2*)(dlp + off) = make_uint2(lo0, lo1);
            }
            __syncthreads();
        }

        uint32_t stA = sb + (uint32_t)(c & 1) * 32768;
#pragma unroll
        for (int ks2 = 0; ks2 < 4; ks2++) {
            uint32_t xA = ((uint32_t)ks2 * 32 + kaddA2) ^ xr;
            uint32_t bbase = bRowB + (uint32_t)ks2 * 2048;
            uint32_t aH0[4], aH1[4], aL0[4], aL1[4], bH[8], bL[8];
            ldmx4(aH0, stA + aRow + xA);
            ldmx4(aH1, stA + aRow + 2048 + xA);
            ldmx4(aL0, stA + 16384 + aRow + xA);
            ldmx4(aL1, stA + 16384 + aRow + 2048 + xA);
            ldmx4t(bH,     stBh + bbase + xB1);
            ldmx4t(bH + 4, stBh + bbase + xB2);
            ldmx4t(bL,     stBl + bbase + xB1);
            ldmx4t(bL + 4, stBl + bbase + xB2);
#pragma unroll
            for (int mf = 0; mf < 2; mf++) {
                const uint32_t* ah = mf ? aH1 : aH0;
                const uint32_t* al = mf ? aL1 : aL0;
#pragma unroll
                for (int nf = 0; nf < 4; nf++) {
                    mma_bf16(acc[mf][nf], ah, bH + nf * 2);
                    mma_bf16(acc[mf][nf], ah, bL + nf * 2);
                    mma_bf16(acc[mf][nf], al, bH + nf * 2);
                }
            }
        }
        __syncthreads();
    }

    // epilogue: write fp32 partial tile
    int g = l >> 2, tg = l & 3;
#pragma unroll
    for (int mf = 0; mf < 2; mf++) {
#pragma unroll
        for (int nf = 0; nf < 4; nf++) {
            int gm = mt * 128 + m0 + mf * 16 + g;
            int gn = nt * 64 + n0 + nf * 8 + tg * 2;
            float* dst = partial + (size_t)ks * 256 * N + (size_t)gm * N + gn;
            *(float2*)dst = make_float2(acc[mf][nf][0], acc[mf][nf][1]);
            *(float2*)(dst + (size_t)8 * N) = make_float2(acc[mf][nf][2], acc[mf][nf][3]);
        }
    }
}

// ================= epilogue: reduce split-K + bias + relu + pack to A blocks =================
__global__ __launch_bounds__(256) void epi_pack(
    const float* __restrict__ partial, const float* __restrict__ bias,
    __nv_bfloat16* __restrict__ outH, __nv_bfloat16* __restrict__ outL)
{
    int nt = blockIdx.x, mt = blockIdx.y;
    int t = threadIdx.x;
    int ml = t >> 1;
    int half = (t & 1) * 32;
    int row = mt * 128 + ml;
    int col0 = nt * 64 + half;
    const float* p = partial + (size_t)row * 1024 + col0;
    size_t blk = ((size_t)mt * gridDim.x + nt) * 8192;
    char* dh = (char*)(outH + blk);
    char* dl = (char*)(outL + blk);
#pragma unroll 4
    for (int i = 0; i < 32; i += 2) {
        float v0 = p[i]     + p[i + 262144]     + p[i + 524288]     + p[i + 786432];
        float v1 = p[i + 1] + p[i + 1 + 262144] + p[i + 1 + 524288] + p[i + 1 + 786432];
        v0 = fmaxf(v0 + bias[col0 + i], 0.0f);
        v1 = fmaxf(v1 + bias[col0 + i + 1], 0.0f);
        uint32_t lo, hi = split_pack(v0, v1, lo);
        uint32_t off = sw128((uint32_t)(ml * 128 + (half + i) * 2));
        *(uint32_t*)(dh + off) = hi;
        *(uint32_t*)(dl + off) = lo;
    }
}

// ================= heads: reduce split-K =================
__global__ __launch_bounds__(1024) void epi_heads(const float* __restrict__ partial)
{
    int idx = blockIdx.x * 1024 + threadIdx.x;
    g_heads[idx] = partial[idx] + partial[idx + 32768] + partial[idx + 65536] + partial[idx + 98304];
}

// ================= heads activations -> rot/trans params =================
__global__ __launch_bounds__(64) void heads_epi(
    const float* __restrict__ bum, const float* __restrict__ buv,
    const float* __restrict__ bgm, const float* __restrict__ bgv,
    const float* __restrict__ eps_u, const float* __restrict__ eps_g)
{
    __shared__ float su[48];
    __shared__ float sg[3];
    int b = blockIdx.x, t = threadIdx.x;
    const float* hr = g_heads + (size_t)b * 128;
    if (t < 48) {
        float umu  = tanhf(hr[t] + bum[t]);
        float up   = hr[48 + t] + buv[t];
        float uvar = expf(up > -6.0f ? up : -6.0f);        // threshold(x,-6,-6)
        su[t] = umu + uvar * eps_u[b * 48 + t];
    } else if (t < 51) {
        int j = t - 48;
        float gmu  = tanhf(hr[96 + j] + bgm[j]);
        float gp   = hr[99 + j] + bgv[j];
        float gvar = expf(gp > -6.0f ? gp : 6.0f);         // threshold(x,-6,6) !
        sg[j] = gmu + gvar * eps_g[b * 3 + j];
    }
    __syncthreads();
    if (t < 16) {
        float a = su[3 * t], tx = su[3 * t + 1], ty = su[3 * t + 2];
        g_params[b * 16 + t] = make_float4(cosf(a), sinf(a), tx, ty);
    } else if (t == 16) {
        g_gpar[b] = make_float4(cosf(sg[0]), sinf(sg[0]), sg[1], sg[2]);
    }
}

// ================= fused composite + global transform =================
// One block per batch. KM row-lerp reuse halves M loads; x staged in smem; global
// resample fused at the end.
__global__ __launch_bounds__(256) void composite_global(
    const float* __restrict__ M, float* __restrict__ out)
{
    __shared__ float  sparts[NP][256];
    __shared__ float  sx[4096];
    __shared__ float4 spar[NP];
    __shared__ float4 sgp;
    int b = blockIdx.x, t = threadIdx.x;
    for (int i = t; i < NP * 256; i += 256) sparts[i >> 8][i & 255] = g_part[i];
    if (t < 16) spar[t] = g_params[b * 16 + t];
    if (t == 16) sgp = g_gpar[b];
    __syncthreads();

    int w  = t & 63;
    int hb = (t >> 6) * 16;
    float num[16], den[16];
#pragma unroll
    for (int i = 0; i < 16; i++) { num[i] = 0.0f; den[i] = 0.0f; }
    float xn = (2 * w + 1) * (1.0f / 64.0f) - 1.0f;

#pragma unroll 1
    for (int k = 0; k < 16; k++) {
        float4 pp = spar[k];
        float c = pp.x, s = pp.y, tx = pp.z, ty = pp.w;
        int sx_ = (k & 3) * 8 - 12;
        int sy_ = (k >> 2) * 8 - 12;

        float fx = fminf(fmaxf(tx * 32.0f, -1e8f), 1e8f);
        float fy = fminf(fmaxf(ty * 32.0f, -1e8f), 1e8f);
        float ffx = floorf(fx), ffy = floorf(fy);
        float wx = fx - ffx, wy = fy - ffy;
        int dx0 = (int)ffx, dy0 = (int)ffy;
        int x0 = w + dx0, xA = x0 + sx_;
        bool vx0 = ((unsigned)x0 < 64u) && ((unsigned)xA < 64u);
        bool vx1 = ((unsigned)(x0 + 1) < 64u) && ((unsigned)(xA + 1) < 64u);
        const float* Mk = M + ((size_t)((b << 4) + k) << 12);

        float gxc = c * xn + tx;
        float gyc = s * xn + ty;
        int iox = 24 - sx_, ioy = 24 - sy_;
        float foxlo = (float)iox - 1.0f, foxhi = (float)iox + 16.0f;
        float foylo = (float)ioy - 1.0f, foyhi = (float)ioy + 16.0f;
        const float* pk = &sparts[k][0];

        // row-lerp with reuse: rows y0 and y0+1 share loads across consecutive i
        auto rowv = [&](int y0) -> float {
            int yA = y0 + sy_;
            float a = 0.0f, bb = 0.0f;
            if (((unsigned)y0 < 64u) & ((unsigned)yA < 64u)) {
                const float* r = Mk + yA * 64 + xA;
                if (vx0) a = r[0];
                if (vx1) bb = r[1];
            }
            return a + wx * (bb - a);
        };
        float prev = rowv(hb + dy0);
#pragma unroll
        for (int i = 0; i < 16; i++) {
            int h = hb + i;
            float cur = rowv(h + dy0 + 1);
            float km = prev + wy * (cur - prev);
            prev = cur;
            den[i] += km;

            float yn  = (2 * h + 1) * (1.0f / 64.0f) - 1.0f;
            float gx  = gxc - s * yn;
            float gy  = gyc + c * yn;
            float ppx = gx * 32.0f + 31.5f;
            float ppy = gy * 32.0f + 31.5f;
            if (ppx > foxlo && ppx < foxhi && ppy > foylo && ppy < foyhi) {
                float fjx = floorf(ppx), fjy = floorf(ppy);
                float ux = ppx - fjx, uy = ppy - fjy;
                int px0 = (int)fjx - iox, py0 = (int)fjy - ioy;
                float p00 = 0.0f, p01 = 0.0f, p10 = 0.0f, p11 = 0.0f;
                if ((unsigned)py0 < 16u) {
                    if ((unsigned)px0 < 16u)       p00 = pk[py0 * 16 + px0];
                    if ((unsigned)(px0 + 1) < 16u) p01 = pk[py0 * 16 + px0 + 1];
                }
                if ((unsigned)(py0 + 1) < 16u) {
                    if ((unsigned)px0 < 16u)       p10 = pk[(py0 + 1) * 16 + px0];
                    if ((unsigned)(px0 + 1) < 16u) p11 = pk[(py0 + 1) * 16 + px0 + 1];
                }
                float q0 = p00 + ux * (p01 - p00);
                float q1 = p10 + ux * (p11 - p10);
                float xp = q0 + uy * (q1 - q0);
                num[i] += xp * km;
            }
        }
    }

#pragma unroll
    for (int i = 0; i < 16; i++) {
        float d = den[i];
        d = (d == 0.0f) ? 1.0f : d;
        sx[(hb + i) * 64 + w] = num[i] / d;
    }
    __syncthreads();

    // global transform from smem
    float4 gp = sgp;
#pragma unroll
    for (int i = 0; i < 16; i++) {
        int h = hb + i;
        float yn = (2 * h + 1) * (1.0f / 64.0f) - 1.0f;
        float gx = gp.x * xn - gp.y * yn + gp.z;
        float gy = gp.y * xn + gp.x * yn + gp.w;
        float px = fminf(fmaxf(gx * 32.0f + 31.5f, -8.0f), 72.0f);
        float py = fminf(fmaxf(gy * 32.0f + 31.5f, -8.0f), 72.0f);
        float fx0 = floorf(px), fy0 = floorf(py);
        float wx = px - fx0, wy = py - fy0;
        int x0 = (int)fx0, y0 = (int)fy0;
        float v00 = 0.0f, v01 = 0.0f, v10 = 0.0f, v11 = 0.0f;
        bool vx0 = (unsigned)x0 < 64u, vx1 = (unsigned)(x0 + 1) < 64u;
        bool vy0 = (unsigned)y0 < 64u, vy1 = (unsigned)(y0 + 1) < 64u;
        if (vx0 && vy0) v00 = sx[y0 * 64 + x0];
        if (vx1 && vy0) v01 = sx[y0 * 64 + x0 + 1];
        if (vx0 && vy1) v10 = sx[(y0 + 1) * 64 + x0];
        if (vx1 && vy1) v11 = sx[(y0 + 1) * 64 + x0 + 1];
        float r0 = v00 + wx * (v01 - v00);
        float r1 = v10 + wx * (v11 - v10);
        out[b * 4096 + h * 64 + w] = r0 + wy * (r1 - r0);
    }
}

// ================= launch =================
extern "C" void kernel_launch(void* const* d_in, const int* in_sizes, int n_in,
                              void* d_out, int out_size)
{
    const float* inputs = (const float*)d_in[0];
    const float* W1     = (const float*)d_in[1];
    const float* b1     = (const float*)d_in[2];
    const float* W2     = (const float*)d_in[3];
    const float* b2     = (const float*)d_in[4];
    const float* Wum    = (const float*)d_in[5];
    const float* bum    = (const float*)d_in[6];
    const float* Wuv    = (const float*)d_in[7];
    const float* buv    = (const float*)d_in[8];
    const float* Wgm    = (const float*)d_in[9];
    const float* bgm    = (const float*)d_in[10];
    const float* Wgv    = (const float*)d_in[11];
    const float* bgv    = (const float*)d_in[12];
    const float* Wz     = (const float*)d_in[13];
    const float* M      = (const float*)d_in[14];
    const float* eps_u  = (const float*)d_in[15];
    const float* eps_g  = (const float*)d_in[16];
    float* out = (float*)d_out;

    const int SMEM_DYN = 131072;
    cudaFuncSetAttribute(mma_gemm<16, true>,  cudaFuncAttributeMaxDynamicSharedMemorySize, SMEM_DYN);
    cudaFuncSetAttribute(mma_gemm<4, true>,   cudaFuncAttributeMaxDynamicSharedMemorySize, SMEM_DYN);
    cudaFuncSetAttribute(mma_gemm<4, false>,  cudaFuncAttributeMaxDynamicSharedMemorySize, SMEM_DYN);

    __nv_bfloat16 *A1h, *A1l, *A2h, *A2l, *A3h, *A3l, *WHh, *WHl;
    float* partial;
    cudaGetSymbolAddress((void**)&A1h, g_A1h); cudaGetSymbolAddress((void**)&A1l, g_A1l);
    cudaGetSymbolAddress((void**)&A2h, g_A2h); cudaGetSymbolAddress((void**)&A2l, g_A2l);
    cudaGetSymbolAddress((void**)&A3h, g_A3h); cudaGetSymbolAddress((void**)&A3l, g_A3l);
    cudaGetSymbolAddress((void**)&WHh, g_WHh); cudaGetSymbolAddress((void**)&WHl, g_WHl);
    cudaGetSymbolAddress((void**)&partial, g_partial);

    part_kernel<<<16, 256>>>(Wz);
    convA_kernel<<<dim3(64, 2), 256>>>(inputs);
    convWH_kernel<<<dim3(2, 16), 256>>>(Wum, Wuv, Wgm, Wgv);

    // GEMM1: [256x4096] x W1[4096x1024], fused conversion, split-K 4
    mma_gemm<16, true><<<dim3(16, 2, 4), 256, SMEM_DYN>>>(
        A1h, A1l, nullptr, nullptr, W1, 1024, partial, 64, 1024);
    epi_pack<<<dim3(16, 2), 256>>>(partial, b1, A2h, A2l);
    // GEMM2: [256x1024] x W2[1024x1024], fused conversion, split-K 4
    mma_gemm<4, true><<<dim3(16, 2, 4), 256, SMEM_DYN>>>(
        A2h, A2l, nullptr, nullptr, W2, 1024, partial, 16, 1024);
    epi_pack<<<dim3(16, 2), 256>>>(partial, b2, A3h, A3l);
    // GEMM3 (heads): [256x1024] x WH[1024x128], pre-converted, split-K 4
    mma_gemm<4, false><<<dim3(2, 2, 4), 256, SMEM_DYN>>>(
        A3h, A3l, WHh, WHl, nullptr, 0, partial, 16, 128);
    epi_heads<<<32, 1024>>>(partial);

    heads_epi<<<BB, 64>>>(bum, buv, bgm, bgv, eps_u, eps_g);
    composite_global<<<BB, 256>>>(M, out);
}